// round 17
// baseline (speedup 1.0000x reference)
#include <cuda_runtime.h>

// Problem constants
#define BB 65536
#define DD 256
#define KK 32
#define TM 64
#define NBLK (BB / TM)   // 1024
#define BD (BB * DD)

// Device scratch (no cudaMalloc allowed)
__device__ float g_G1[KK * KK];                    // W . U^T
__device__ float g_G2[KK * KK];                    // W . W^T
__device__ float g_AL[KK];                         // alpha_k
__device__ __align__(16) float g_uhat[KK * DD];    // [k][d]
__device__ __align__(16) float g_WT[DD * KK];      // W transposed [d][k]
__device__ unsigned int g_done;                    // gram-completion flag (memset 0 per launch)

typedef unsigned long long ull;

// ---------- f32x2 helpers ----------
__device__ __forceinline__ ull ffma2(ull a, ull b, ull c) {
    ull d;
    asm("fma.rn.f32x2 %0, %1, %2, %3;" : "=l"(d) : "l"(a), "l"(b), "l"(c));
    return d;
}
__device__ __forceinline__ ull fadd2(ull a, ull b) {
    ull d;
    asm("add.rn.f32x2 %0, %1, %2;" : "=l"(d) : "l"(a), "l"(b));
    return d;
}
__device__ __forceinline__ ull packf2(float x, float y) {
    ull r;
    asm("mov.b64 %0, {%1, %2};" : "=l"(r) : "f"(x), "f"(y));
    return r;
}
__device__ __forceinline__ void cpasync16(void* smem_dst, const void* gsrc) {
    unsigned sa = (unsigned)__cvta_generic_to_shared(smem_dst);
    asm volatile("cp.async.cg.shared.global [%0], [%1], 16;" :: "r"(sa), "l"(gsrc));
}
__device__ __forceinline__ void cpasync_commit() {
    asm volatile("cp.async.commit_group;");
}
__device__ __forceinline__ void cpasync_waitall() {
    asm volatile("cp.async.wait_group 0;" ::: "memory");
}

// fast accurate tanh: 1 - 2/(exp(2x)+1)
__device__ __forceinline__ float ftanh(float x) {
    float e = __expf(2.0f * x);
    return 1.0f - __fdividef(2.0f, e + 1.0f);
}
__device__ __forceinline__ float softplus(float x) {
    return fmaxf(x, 0.f) + log1pf(expf(-fabsf(x)));
}

// ---------- Fused kernel ----------
// smem (floats):
//  XS : 0      X tile [r][d] stride 260 (float4-clean)    = 16640
//  WT : 16640  W^T [d][k] stride 36 (dead after phase 1)  = 9216
//    after phase 1 this region is reused:
//      B  = OFF_WT         partial-C buffer B [r][k] stride 36 (2304)
//      UH = OFF_WT         uhat [k][d] linear (8192) — low 2304 staged
//                          only AFTER B is consumed into registers
//      AS = OFF_WT + 8192  A[k][j] (1024)
//  CS : 25856  partial A / C [r][k] stride 34; t in place = 2176
//  BS : 28032  b[32],  AL : 28064 alpha[32]
// total 28096 floats = 112384 B -> 2 blocks/SM
#define OFF_XS 0
#define OFF_WT 16640
#define OFF_AS (16640 + 8192)
#define OFF_CS 25856
#define OFF_BS 28032
#define OFF_AL 28064
#define SMEM_FLOATS 28096
#define B_F4 576          // B extent in float4 (64*36/4)
#define UH_F4 2048        // uhat extent in float4

__global__ __launch_bounds__(256, 2)
void nf_fused(const float* __restrict__ X, const float* __restrict__ uu,
              const float* __restrict__ w, const float* __restrict__ bvec,
              float* __restrict__ out) {
    extern __shared__ float sm[];
    float* XS = sm + OFF_XS;
    float* WT = sm + OFF_WT;     // also B / UH after phase 1
    float* AS = sm + OFF_AS;
    float* CS = sm + OFF_CS;
    float* BS = sm + OFF_BS;
    float* AL = sm + OFF_AL;

    const int t = threadIdx.x;
    const int bid = blockIdx.x;
    const int r0 = bid * TM;
    const int lane = t & 31, wp = t >> 5;

    // ---- Stage X tile via cp.async (latency hides under gram/spin) ----
    {
        const float4* Xb4 = (const float4*)(X + (size_t)r0 * DD);
        #pragma unroll
        for (int i = t; i < TM * DD / 4; i += 256) {
            int r = i >> 6, d4 = i & 63;
            cpasync16(&XS[r * 260 + d4 * 4], &Xb4[i]);
        }
        cpasync_commit();
    }

    // ---- Blocks 0..31: gram work for k = bid ----
    if (bid < KK) {
        const int k = bid;
        float* ws  = WT;        // scratch (overwritten later by real WT)
        float* red = CS;        // reduce scratch

        float wv_t = w[k * DD + t];
        float uv_t = uu[k * DD + t];
        ws[t] = wv_t;
        g_WT[t * KK + k] = wv_t;

        {
            float p = wv_t * uv_t;
            float q = wv_t * wv_t;
            #pragma unroll
            for (int o = 16; o; o >>= 1) {
                p += __shfl_xor_sync(0xffffffffu, p, o);
                q += __shfl_xor_sync(0xffffffffu, q, o);
            }
            if (lane == 0) { red[wp * 2] = p; red[wp * 2 + 1] = q; }
        }
        __syncthreads();
        if (t == 0) {
            float wu = 0.f, ww = 0.f;
            #pragma unroll
            for (int i = 0; i < 8; ++i) { wu += red[2 * i]; ww += red[2 * i + 1]; }
            float a = (softplus(wu) - 1.0f - wu) / ww;
            red[16] = a;
            g_AL[k] = a;
        }
        __syncthreads();
        g_uhat[k * DD + t] = fmaf(red[16], wv_t, uv_t);

        // Gram rows: warp wp -> j = wp*4..wp*4+3
        #pragma unroll
        for (int jj = 0; jj < 4; ++jj) {
            const int j = wp * 4 + jj;
            const float4* up4 = (const float4*)(uu + j * DD) + lane * 2;
            const float4* wp4 = (const float4*)(w  + j * DD) + lane * 2;
            const float*  wsp = ws + lane * 8;
            float4 ua = up4[0], ub = up4[1];
            float4 wa = wp4[0], wb = wp4[1];
            float p1 = 0.f, p2 = 0.f;
            #pragma unroll
            for (int i = 0; i < 4; ++i) {
                float wv0 = wsp[i], wv1 = wsp[4 + i];
                p1 = fmaf(wv0, (&ua.x)[i], p1);
                p2 = fmaf(wv0, (&wa.x)[i], p2);
                p1 = fmaf(wv1, (&ub.x)[i], p1);
                p2 = fmaf(wv1, (&wb.x)[i], p2);
            }
            #pragma unroll
            for (int o = 16; o; o >>= 1) {
                p1 += __shfl_xor_sync(0xffffffffu, p1, o);
                p2 += __shfl_xor_sync(0xffffffffu, p2, o);
            }
            if (lane == 0) {
                g_G1[k * KK + j] = p1;
                g_G2[k * KK + j] = p2;
            }
        }
        __threadfence();
        __syncthreads();
        if (t == 0) atomicAdd(&g_done, 1u);
    }

    // ---- Wait for gram publication ----
    if (t == 0) {
        while (atomicAdd(&g_done, 0u) < (unsigned)KK) __nanosleep(64);
    }
    __syncthreads();

    // ---- Stage W^T (stride 36) via cp.async; b, alpha ----
    {
        const float4* W4 = (const float4*)g_WT;
        #pragma unroll
        for (int i = t; i < KK * DD / 4; i += 256) {
            int d = i >> 3, k4 = i & 7;
            cpasync16(&WT[d * 36 + k4 * 4], &W4[i]);
        }
        cpasync_commit();
        if (t < KK) { BS[t] = bvec[t]; AL[t] = g_AL[t]; }
    }
    cpasync_waitall();
    __syncthreads();

    // ---- Phase 1: partial C = X . W^T ----
    // warp = (kh in {0,1}, dq in {0..3}); 16 k, 64 d, rows lane & lane+32.
    const int kh = wp >> 2, dq = wp & 3;
    const int k0 = kh * 16;
    ull c0[8], c1[8];
    {
        const int d0 = dq * 64;
        #pragma unroll
        for (int q = 0; q < 8; ++q) { c0[q] = 0ull; c1[q] = 0ull; }
        const float* x0p = XS + lane * 260 + d0;
        const float* x1p = XS + (lane + 32) * 260 + d0;
        const float* wbase = WT + k0;
        #pragma unroll 4
        for (int dd = 0; dd < 64; dd += 4) {
            float4 xa = *(const float4*)(x0p + dd);
            float4 xb = *(const float4*)(x1p + dd);
            #pragma unroll
            for (int j = 0; j < 4; ++j) {
                const float* wd = wbase + (d0 + dd + j) * 36;
                ulonglong2 w0 = *(const ulonglong2*)(wd);
                ulonglong2 w1 = *(const ulonglong2*)(wd + 4);
                ulonglong2 w2 = *(const ulonglong2*)(wd + 8);
                ulonglong2 w3 = *(const ulonglong2*)(wd + 12);
                float xj0 = (&xa.x)[j];
                float xj1 = (&xb.x)[j];
                ull p0 = packf2(xj0, xj0);
                ull p1 = packf2(xj1, xj1);
                c0[0] = ffma2(p0, w0.x, c0[0]);  c1[0] = ffma2(p1, w0.x, c1[0]);
                c0[1] = ffma2(p0, w0.y, c0[1]);  c1[1] = ffma2(p1, w0.y, c1[1]);
                c0[2] = ffma2(p0, w1.x, c0[2]);  c1[2] = ffma2(p1, w1.x, c1[2]);
                c0[3] = ffma2(p0, w1.y, c0[3]);  c1[3] = ffma2(p1, w1.y, c1[3]);
                c0[4] = ffma2(p0, w2.x, c0[4]);  c1[4] = ffma2(p1, w2.x, c1[4]);
                c0[5] = ffma2(p0, w2.y, c0[5]);  c1[5] = ffma2(p1, w2.y, c1[5]);
                c0[6] = ffma2(p0, w3.x, c0[6]);  c1[6] = ffma2(p1, w3.x, c1[6]);
                c0[7] = ffma2(p0, w3.y, c0[7]);  c1[7] = ffma2(p1, w3.y, c1[7]);
            }
        }
    }
    // dq0 stores partial A into CS (dedicated region, no barrier needed yet)
    if (dq == 0) {
        #pragma unroll
        for (int q = 0; q < 8; ++q) {
            *(ull*)&CS[lane * 34 + k0 + 2 * q]        = c0[q];
            *(ull*)&CS[(lane + 32) * 34 + k0 + 2 * q] = c1[q];
        }
    }
    __syncthreads();   // bar1: all WT/XS reads done; WT region reusable

    float* Bp = WT;    // partial buffer B, [r][k] stride 36
    if (dq == 1) {
        #pragma unroll
        for (int q = 0; q < 8; ++q) {
            *(ull*)&Bp[lane * 36 + k0 + 2 * q]        = c0[q];
            *(ull*)&Bp[(lane + 32) * 36 + k0 + 2 * q] = c1[q];
        }
    }
    __syncthreads();   // bar2: A and B base partials visible

    if (dq == 2) {
        #pragma unroll
        for (int q = 0; q < 8; ++q) {
            ull* a0 = (ull*)&CS[lane * 34 + k0 + 2 * q];
            ull* a1 = (ull*)&CS[(lane + 32) * 34 + k0 + 2 * q];
            *a0 = fadd2(*a0, c0[q]);
            *a1 = fadd2(*a1, c1[q]);
        }
    } else if (dq == 3) {
        #pragma unroll
        for (int q = 0; q < 8; ++q) {
            ull* b0 = (ull*)&Bp[lane * 36 + k0 + 2 * q];
            ull* b1 = (ull*)&Bp[(lane + 32) * 36 + k0 + 2 * q];
            *b0 = fadd2(*b0, c0[q]);
            *b1 = fadd2(*b1, c1[q]);
        }
    } else {
        // dq 0,1 warps (4 warps = 128 threads): stage AS = G1 + alpha_j*G2
        int pid = (kh * 2 + dq) * 32 + lane;   // 0..127
        for (int e = pid; e < KK * KK; e += 128)
            AS[e] = fmaf(AL[e & 31], g_G2[e], g_G1[e]);
    }
    __syncthreads();   // bar3: C = A(+)B complete; AS ready

    // ---- Phase 2a: rows pull B into registers; others stage uhat-hi ----
    float br[KK];
    if (t < TM) {
        #pragma unroll
        for (int j = 0; j < 8; ++j)
            *(float4*)&br[4 * j] = *(const float4*)&Bp[t * 36 + 4 * j];
    } else {
        const float4* U4 = (const float4*)g_uhat;
        float4* UH4 = (float4*)WT;
        for (int i = B_F4 + (t - TM); i < UH_F4; i += 256 - TM)
            UH4[i] = U4[i];
    }
    __syncthreads();   // bar4: B consumed; low UH region now writable

    // ---- Phase 2b: recurrence (warps 0-1); uhat-lo stage + X hoist (2-7) ----
    ulonglong2 a[8][2];
    const int col0 = lane * 4, col1 = 128 + lane * 4;
    const int rb = wp * 8;

    if (t < TM) {
        const int row = t;
        float tl[KK];
        #pragma unroll
        for (int k = 0; k < KK; ++k) {
            float la[4];
            la[0] = CS[row * 34 + k] + br[k] + BS[k];
            la[1] = 0.f; la[2] = 0.f; la[3] = 0.f;
            #pragma unroll
            for (int j = 0; j < k; ++j)
                la[j & 3] = fmaf(AS[k * KK + j], tl[j], la[j & 3]);
            float lin = (la[0] + la[1]) + (la[2] + la[3]);
            float tk = ftanh(lin);
            tl[k] = tk;
            CS[row * 34 + k] = tk;   // overwrite C with t (slot is dead)
            float akk = AS[k * (KK + 1)];
            out[BD + k * BB + r0 + row] =
                __logf(fabsf(fmaf(1.0f - tk * tk, akk, 1.0f)) + 1e-8f);
        }
    } else {
        const float4* U4 = (const float4*)g_uhat;
        float4* UH4 = (float4*)WT;
        for (int i = t - TM; i < B_F4; i += 256 - TM)
            UH4[i] = U4[i];
    }
    // hoisted phase-3 X-init (warps 2-7 overlap recurrence; 0-1 after)
    if (t >= TM) {
        #pragma unroll
        for (int r = 0; r < 8; ++r) {
            const float* xr = X + (size_t)(r0 + rb + r) * DD;
            a[r][0] = *(const ulonglong2*)(xr + col0);
            a[r][1] = *(const ulonglong2*)(xr + col1);
        }
    }
    __syncthreads();   // bar5
    if (t < TM) {
        #pragma unroll
        for (int r = 0; r < 8; ++r) {
            const float* xr = X + (size_t)(r0 + rb + r) * DD;
            a[r][0] = *(const ulonglong2*)(xr + col0);
            a[r][1] = *(const ulonglong2*)(xr + col1);
        }
    }

    // ---- Phase 3: Z = X + T . Uhat ----
    {
        const float* UH = WT;
        #pragma unroll 4
        for (int khh = 0; khh < 16; ++khh) {     // 2 k per step
            const int kk0 = khh * 2;
            float2 tv[8];
            #pragma unroll
            for (int r = 0; r < 8; ++r)
                tv[r] = *(const float2*)&CS[(rb + r) * 34 + kk0];
            #pragma unroll
            for (int kk = 0; kk < 2; ++kk) {
                const int k = kk0 + kk;
                ulonglong2 u0 = *(const ulonglong2*)&UH[k * DD + col0];
                ulonglong2 u1 = *(const ulonglong2*)&UH[k * DD + col1];
                #pragma unroll
                for (int r = 0; r < 8; ++r) {
                    float ts = kk ? tv[r].y : tv[r].x;
                    ull tt = packf2(ts, ts);
                    a[r][0].x = ffma2(tt, u0.x, a[r][0].x);
                    a[r][0].y = ffma2(tt, u0.y, a[r][0].y);
                    a[r][1].x = ffma2(tt, u1.x, a[r][1].x);
                    a[r][1].y = ffma2(tt, u1.y, a[r][1].y);
                }
            }
        }
        #pragma unroll
        for (int r = 0; r < 8; ++r) {
            float* zr = out + (size_t)(r0 + rb + r) * DD;
            *(ulonglong2*)(zr + col0) = a[r][0];
            *(ulonglong2*)(zr + col1) = a[r][1];
        }
    }
}

extern "C" void kernel_launch(void* const* d_in, const int* in_sizes, int n_in,
                              void* d_out, int out_size) {
    const float* X = (const float*)d_in[0];
    // d_in[1] = h (unused)
    const float* u = (const float*)d_in[2];
    const float* w = (const float*)d_in[3];
    const float* b = (const float*)d_in[4];
    float* out = (float*)d_out;

    cudaFuncSetAttribute(nf_fused, cudaFuncAttributeMaxDynamicSharedMemorySize,
                         SMEM_FLOATS * (int)sizeof(float));

    // reset gram-completion flag (graph-capturable, no allocation)
    void* flag_ptr = nullptr;
    cudaGetSymbolAddress(&flag_ptr, g_done);
    cudaMemsetAsync(flag_ptr, 0, sizeof(unsigned int));

    nf_fused<<<NBLK, 256, SMEM_FLOATS * sizeof(float)>>>(X, u, w, b, out);
}